// round 3
// baseline (speedup 1.0000x reference)
#include <cuda_runtime.h>
#include <cuda_bf16.h>
#include <math.h>

// Problem dims (fixed by setup_inputs)
#define BB   4
#define NPTS 2048
#define LL   4096      // 2*NPTS
#define EE   128
#define DI   256
#define DS   16
#define DR   8
#define NXD  40        // DR + 2*DS
#define DC   4
#define NC   40
#define BL   (BB*LL)   // 16384 rows
#define NCH  32        // scan chunks
#define CL   128       // chunk length (NCH*CL == LL)
#define NCHAN (BB*DI)  // 1024 scan channels

// -------- scratch (static device globals; no runtime allocation) --------
__device__ float g_h   [(size_t)BL*EE];
__device__ float g_xn  [(size_t)BL*EE];
__device__ float g_uz  [(size_t)BL*2*DI];
__device__ float g_uc  [(size_t)BL*DI];
__device__ float g_xdbl[(size_t)BL*NXD];
__device__ float g_delta[(size_t)BL*DI];
__device__ float g_y   [(size_t)BL*DI];
__device__ float g_acc [BB*EE];
__device__ float g_hend[(size_t)NCHAN*NCH*DS];
__device__ float g_h0  [(size_t)NCHAN*NCH*DS];
__device__ float g_sd  [(size_t)NCHAN*NCH];

__device__ __forceinline__ float siluf(float x) { return x / (1.f + expf(-x)); }
__device__ __forceinline__ float softplusf(float x) {
    return fmaxf(x, 0.f) + log1pf(expf(-fabsf(x)));
}

// -------- 0) gather + positional embed --------
__global__ void k_embed(const float* __restrict__ x,
                        const int* __restrict__ oh, const int* __restrict__ ot,
                        const float* __restrict__ pew, const float* __restrict__ peb,
                        const float* __restrict__ gamma, const float* __restrict__ beta)
{
    int bl = blockIdx.x;
    int b = bl >> 12, l = bl & (LL-1);
    int e = threadIdx.x;
    int gi, idx;
    if (l < NPTS) { gi = 0; idx = oh[b*NPTS + l]; }
    else          { gi = 1; idx = ot[b*NPTS + (l - NPTS)]; }
    const float* p = x + ((size_t)b*NPTS + idx)*3;
    float px = p[0], py = p[1], pz = p[2];
    float v = pew[e*3+0]*px + pew[e*3+1]*py + pew[e*3+2]*pz + peb[e];
    v = v * gamma[gi*EE + e] + beta[gi*EE + e];
    g_h[(size_t)bl*EE + e] = v;
}

// -------- 1) LayerNorm over E=128 --------
__global__ void k_ln(const float* __restrict__ g, const float* __restrict__ bbv)
{
    int row = blockIdx.x;
    int e   = threadIdx.x;
    float v = g_h[(size_t)row*EE + e];
    float a = v, a2 = v*v;
    #pragma unroll
    for (int o = 16; o > 0; o >>= 1) {
        a  += __shfl_xor_sync(~0u, a,  o);
        a2 += __shfl_xor_sync(~0u, a2, o);
    }
    __shared__ float s1[4], s2[4];
    int w = e >> 5;
    if ((e & 31) == 0) { s1[w] = a; s2[w] = a2; }
    __syncthreads();
    float sum  = s1[0] + s1[1] + s1[2] + s1[3];
    float sumq = s2[0] + s2[1] + s2[2] + s2[3];
    float m   = sum  * (1.f/EE);
    float var = sumq * (1.f/EE) - m*m;
    float xn = (v - m) * rsqrtf(var + 1e-5f) * g[e] + bbv[e];
    g_xn[(size_t)row*EE + e] = xn;
}

// ======== big SGEMM: C[M,N] (+)= A[M,K] * W[N,K]^T ========
// BM=128, BN=128, BK=8, 256 threads, 8x8 micro-tile (split quadrants),
// double-buffered shared memory. Requires M%128==0, N%128==0, K%8==0.
__global__ __launch_bounds__(256) void k_sgemm_big(
    const float* __restrict__ A, const float* __restrict__ W,
    float* __restrict__ C, int M, int N, int K, int accum)
{
    __shared__ float As[2][8][128];
    __shared__ float Ws[2][8][128];
    int tid = threadIdx.x;
    int bm = blockIdx.y * 128;
    int bn = blockIdx.x * 128;

    // global load mapping: each thread loads one float4 of A and one of W
    int lr = tid >> 1;             // row in tile 0..127
    int lk = (tid & 1) * 4;        // k offset 0 or 4

    // compute mapping
    int tx = tid & 15, ty = tid >> 4;
    int r0 = ty * 4, r1 = ty * 4 + 64;
    int c0 = tx * 4, c1 = tx * 4 + 64;

    float acc[8][8];
    #pragma unroll
    for (int i = 0; i < 8; i++)
        #pragma unroll
        for (int j = 0; j < 8; j++) acc[i][j] = 0.f;

    const float* Aptr = A + (size_t)(bm + lr)*K + lk;
    const float* Wptr = W + (size_t)(bn + lr)*K + lk;

    int iters = K >> 3;
    float4 pa = *(const float4*)Aptr;
    float4 pw = *(const float4*)Wptr;

    // store tile 0
    As[0][lk+0][lr] = pa.x; As[0][lk+1][lr] = pa.y;
    As[0][lk+2][lr] = pa.z; As[0][lk+3][lr] = pa.w;
    Ws[0][lk+0][lr] = pw.x; Ws[0][lk+1][lr] = pw.y;
    Ws[0][lk+2][lr] = pw.z; Ws[0][lk+3][lr] = pw.w;
    __syncthreads();

    for (int t = 0; t < iters; t++) {
        int cur = t & 1, nxt = cur ^ 1;
        if (t + 1 < iters) {
            pa = *(const float4*)(Aptr + (t+1)*8);
            pw = *(const float4*)(Wptr + (t+1)*8);
        }
        #pragma unroll
        for (int k = 0; k < 8; k++) {
            float4 a0 = *(const float4*)&As[cur][k][r0];
            float4 a1 = *(const float4*)&As[cur][k][r1];
            float4 b0 = *(const float4*)&Ws[cur][k][c0];
            float4 b1 = *(const float4*)&Ws[cur][k][c1];
            float av[8] = {a0.x,a0.y,a0.z,a0.w, a1.x,a1.y,a1.z,a1.w};
            float bv[8] = {b0.x,b0.y,b0.z,b0.w, b1.x,b1.y,b1.z,b1.w};
            #pragma unroll
            for (int i = 0; i < 8; i++)
                #pragma unroll
                for (int j = 0; j < 8; j++)
                    acc[i][j] += av[i] * bv[j];
        }
        if (t + 1 < iters) {
            As[nxt][lk+0][lr] = pa.x; As[nxt][lk+1][lr] = pa.y;
            As[nxt][lk+2][lr] = pa.z; As[nxt][lk+3][lr] = pa.w;
            Ws[nxt][lk+0][lr] = pw.x; Ws[nxt][lk+1][lr] = pw.y;
            Ws[nxt][lk+2][lr] = pw.z; Ws[nxt][lk+3][lr] = pw.w;
            __syncthreads();
        }
    }

    // epilogue
    #pragma unroll
    for (int i = 0; i < 8; i++) {
        int row = bm + (i < 4 ? r0 + i : r1 + i - 4);
        float* crow = C + (size_t)row*N + bn;
        float4 v0 = make_float4(acc[i][0], acc[i][1], acc[i][2], acc[i][3]);
        float4 v1 = make_float4(acc[i][4], acc[i][5], acc[i][6], acc[i][7]);
        if (accum) {
            float4 o0 = *(float4*)(crow + c0);
            float4 o1 = *(float4*)(crow + c1);
            v0.x += o0.x; v0.y += o0.y; v0.z += o0.z; v0.w += o0.w;
            v1.x += o1.x; v1.y += o1.y; v1.z += o1.z; v1.w += o1.w;
        }
        *(float4*)(crow + c0) = v0;
        *(float4*)(crow + c1) = v1;
    }
}

// -------- small SGEMM (for xproj, N=40) --------
__global__ void k_sgemm_nt(const float* __restrict__ A, const float* __restrict__ W,
                           float* __restrict__ C, int M, int N, int K)
{
    __shared__ float As[16][64];
    __shared__ float Ws[16][64];
    int bm = blockIdx.y * 64;
    int bn = blockIdx.x * 64;
    int tid = threadIdx.x;
    int tx = tid & 15, ty = tid >> 4;
    int la  = tid * 4;
    int lam = la >> 4, lak = la & 15;

    float acc[4][4];
    #pragma unroll
    for (int i = 0; i < 4; i++)
        #pragma unroll
        for (int j = 0; j < 4; j++) acc[i][j] = 0.f;

    for (int k0 = 0; k0 < K; k0 += 16) {
        float4 va = make_float4(0,0,0,0), vw = make_float4(0,0,0,0);
        int gm = bm + lam;
        if (gm < M) va = *(const float4*)(A + (size_t)gm*K + k0 + lak);
        int gn = bn + lam;
        if (gn < N) vw = *(const float4*)(W + (size_t)gn*K + k0 + lak);
        __syncthreads();
        As[lak+0][lam] = va.x; As[lak+1][lam] = va.y;
        As[lak+2][lam] = va.z; As[lak+3][lam] = va.w;
        Ws[lak+0][lam] = vw.x; Ws[lak+1][lam] = vw.y;
        Ws[lak+2][lam] = vw.z; Ws[lak+3][lam] = vw.w;
        __syncthreads();
        #pragma unroll
        for (int k = 0; k < 16; k++) {
            float ar[4], wr[4];
            *(float4*)ar = *(const float4*)&As[k][ty*4];
            *(float4*)wr = *(const float4*)&Ws[k][tx*4];
            #pragma unroll
            for (int i = 0; i < 4; i++)
                #pragma unroll
                for (int j = 0; j < 4; j++)
                    acc[i][j] += ar[i] * wr[j];
        }
    }
    #pragma unroll
    for (int i = 0; i < 4; i++) {
        int row = bm + ty*4 + i;
        if (row >= M) continue;
        #pragma unroll
        for (int j = 0; j < 4; j++) {
            int col = bn + tx*4 + j;
            if (col >= N) continue;
            C[(size_t)row*N + col] = acc[i][j];
        }
    }
}

// -------- 2) depthwise causal conv (width 4) + SiLU --------
__global__ void k_conv(const float* __restrict__ cw, const float* __restrict__ cb)
{
    int row = blockIdx.x;
    int d   = threadIdx.x;
    int b = row >> 12, l = row & (LL-1);
    const float* u = g_uz;
    size_t base = ((size_t)b*LL)*(2*DI) + d;
    float w0 = cw[d*DC+0], w1 = cw[d*DC+1], w2 = cw[d*DC+2], w3 = cw[d*DC+3];
    float acc = cb[d];
    if (l >= 3) acc += u[base + (size_t)(l-3)*(2*DI)] * w0;
    if (l >= 2) acc += u[base + (size_t)(l-2)*(2*DI)] * w1;
    if (l >= 1) acc += u[base + (size_t)(l-1)*(2*DI)] * w2;
    acc += u[base + (size_t)l*(2*DI)] * w3;
    g_uc[(size_t)row*DI + d] = siluf(acc);
}

// -------- 3) delta = softplus(dt @ dtw^T + dtb) --------
__global__ void k_delta(const float* __restrict__ dtw, const float* __restrict__ dtb)
{
    int row = blockIdx.x;
    int d   = threadIdx.x;
    __shared__ float dts[DR];
    if (d < DR) dts[d] = g_xdbl[(size_t)row*NXD + d];
    __syncthreads();
    float acc = dtb[d];
    #pragma unroll
    for (int r = 0; r < DR; r++) acc += dts[r] * dtw[d*DR + r];
    g_delta[(size_t)row*DI + d] = softplusf(acc);
}

// -------- 4a) chunk scan pass A --------
__global__ void k_scanA(const float* __restrict__ Alog)
{
    int w    = blockIdx.x * 8 + (threadIdx.x >> 5);
    int lane = threadIdx.x & 31;
    int grp  = lane >> 4;
    int s    = lane & 15;
    int pair = w & 511;
    int c    = w >> 9;
    int chan = pair*2 + grp;
    int b = chan >> 8, d = chan & 255;

    float A = -expf(Alog[d*DS + s]);
    float h = 0.f, sd = 0.f;

    size_t base_du = (size_t)b*LL*DI + d;
    size_t base_x  = (size_t)b*LL*NXD;
    int t0 = c*CL;

    #pragma unroll 4
    for (int tt = 0; tt < CL; tt++) {
        int t = t0 + tt;
        float delta = g_delta[base_du + (size_t)t*DI];
        float u     = g_uc   [base_du + (size_t)t*DI];
        float Bt    = g_xdbl [base_x + (size_t)t*NXD + DR + s];
        float a = expf(delta * A);
        h = a*h + (delta*u)*Bt;
        sd += delta;
    }
    g_hend[((size_t)chan*NCH + c)*DS + s] = h;
    if (s == 0) g_sd[(size_t)chan*NCH + c] = sd;
}

// -------- 4b) stitch chunk initial states --------
__global__ void k_scanB(const float* __restrict__ Alog)
{
    int w    = blockIdx.x * 8 + (threadIdx.x >> 5);
    int lane = threadIdx.x & 31;
    int grp  = lane >> 4;
    int s    = lane & 15;
    int chan = w*2 + grp;
    int d = chan & 255;

    float A = -expf(Alog[d*DS + s]);
    float h0 = 0.f;
    size_t base = (size_t)chan*NCH;
    for (int c = 0; c < NCH; c++) {
        g_h0[(base + c)*DS + s] = h0;
        float P = expf(A * g_sd[base + c]);
        h0 = P*h0 + g_hend[(base + c)*DS + s];
    }
}

// -------- 4c) chunk scan pass C --------
__global__ void k_scanC(const float* __restrict__ Alog, const float* __restrict__ Dpv)
{
    int w    = blockIdx.x * 8 + (threadIdx.x >> 5);
    int lane = threadIdx.x & 31;
    int grp  = lane >> 4;
    int s    = lane & 15;
    int pair = w & 511;
    int c    = w >> 9;
    int chan = pair*2 + grp;
    int b = chan >> 8, d = chan & 255;

    float A  = -expf(Alog[d*DS + s]);
    float Dd = Dpv[d];
    float h  = g_h0[((size_t)chan*NCH + c)*DS + s];

    size_t base_du = (size_t)b*LL*DI + d;
    size_t base_x  = (size_t)b*LL*NXD;
    size_t base_z  = (size_t)b*LL*(2*DI) + DI + d;
    int t0 = c*CL;

    #pragma unroll 2
    for (int tt = 0; tt < CL; tt++) {
        int t = t0 + tt;
        float delta = g_delta[base_du + (size_t)t*DI];
        float u     = g_uc   [base_du + (size_t)t*DI];
        float Bt    = g_xdbl [base_x + (size_t)t*NXD + DR + s];
        float Ct    = g_xdbl [base_x + (size_t)t*NXD + DR + DS + s];
        float a = expf(delta * A);
        h = a*h + (delta*u)*Bt;
        float p = h * Ct;
        p += __shfl_xor_sync(~0u, p, 8, 16);
        p += __shfl_xor_sync(~0u, p, 4, 16);
        p += __shfl_xor_sync(~0u, p, 2, 16);
        p += __shfl_xor_sync(~0u, p, 1, 16);
        if (s == 0) {
            float z = g_uz[base_z + (size_t)t*(2*DI)];
            float y = p + Dd*u;
            y *= siluf(z);
            g_y[base_du + (size_t)t*DI] = y;
        }
    }
}

// -------- 5) final: zero accum, LN+mean accumulate, fc --------
__global__ void k_zero()
{
    int t = threadIdx.x;
    if (t < BB*EE) g_acc[t] = 0.f;
}

__global__ void k_finacc(const float* __restrict__ gg, const float* __restrict__ gb)
{
    int b     = blockIdx.x >> 4;
    int chunk = blockIdx.x & 15;
    int w    = threadIdx.x >> 5;
    int lane = threadIdx.x & 31;
    float g0 = gg[lane], g1 = gg[lane+32], g2 = gg[lane+64], g3 = gg[lane+96];
    float b0 = gb[lane], b1 = gb[lane+32], b2 = gb[lane+64], b3 = gb[lane+96];
    float a0=0.f, a1=0.f, a2=0.f, a3=0.f;
    for (int j = 0; j < 32; j++) {
        int l = chunk*256 + j*8 + w;
        const float* row = g_h + ((size_t)b*LL + l)*EE;
        float x0 = row[lane], x1 = row[lane+32], x2 = row[lane+64], x3 = row[lane+96];
        float sv = x0+x1+x2+x3;
        float sq = x0*x0 + x1*x1 + x2*x2 + x3*x3;
        #pragma unroll
        for (int o = 16; o > 0; o >>= 1) {
            sv += __shfl_xor_sync(~0u, sv, o);
            sq += __shfl_xor_sync(~0u, sq, o);
        }
        float m   = sv * (1.f/EE);
        float var = sq * (1.f/EE) - m*m;
        float inv = rsqrtf(var + 1e-5f);
        a0 += (x0-m)*inv*g0 + b0;
        a1 += (x1-m)*inv*g1 + b1;
        a2 += (x2-m)*inv*g2 + b2;
        a3 += (x3-m)*inv*g3 + b3;
    }
    atomicAdd(&g_acc[b*EE + lane     ], a0);
    atomicAdd(&g_acc[b*EE + lane + 32], a1);
    atomicAdd(&g_acc[b*EE + lane + 64], a2);
    atomicAdd(&g_acc[b*EE + lane + 96], a3);
}

__global__ void k_fc(const float* __restrict__ fcw, const float* __restrict__ fcb,
                     float* __restrict__ out)
{
    int t = threadIdx.x;
    if (t >= BB*NC) return;
    int b = t / NC, c = t % NC;
    float acc = 0.f;
    #pragma unroll 4
    for (int e = 0; e < EE; e++) acc += g_acc[b*EE + e] * fcw[c*EE + e];
    out[t] = acc * (1.f/LL) + fcb[c];
}

// ----------------------------------------------------------------------------
extern "C" void kernel_launch(void* const* d_in, const int* in_sizes, int n_in,
                              void* d_out, int out_size)
{
    const float* x        = (const float*)d_in[0];
    const int*   order_h  = (const int*)  d_in[1];
    const int*   order_t  = (const int*)  d_in[2];
    const float* pe_w     = (const float*)d_in[3];
    const float* pe_b     = (const float*)d_in[4];
    const float* gamma    = (const float*)d_in[5];
    const float* beta     = (const float*)d_in[6];
    const float* ln_g     = (const float*)d_in[7];
    const float* ln_b     = (const float*)d_in[8];
    const float* inproj_w = (const float*)d_in[9];
    const float* conv_w   = (const float*)d_in[10];
    const float* conv_b   = (const float*)d_in[11];
    const float* xproj_w  = (const float*)d_in[12];
    const float* dtproj_w = (const float*)d_in[13];
    const float* dtproj_b = (const float*)d_in[14];
    const float* A_log    = (const float*)d_in[15];
    const float* Dp       = (const float*)d_in[16];
    const float* outproj_w= (const float*)d_in[17];
    const float* hn_g     = (const float*)d_in[18];
    const float* hn_b     = (const float*)d_in[19];
    const float* fc_w     = (const float*)d_in[20];
    const float* fc_b     = (const float*)d_in[21];
    float* out = (float*)d_out;

    float *p_xn, *p_uz, *p_uc, *p_xdbl, *p_y, *p_h;
    cudaGetSymbolAddress((void**)&p_xn,   g_xn);
    cudaGetSymbolAddress((void**)&p_uz,   g_uz);
    cudaGetSymbolAddress((void**)&p_uc,   g_uc);
    cudaGetSymbolAddress((void**)&p_xdbl, g_xdbl);
    cudaGetSymbolAddress((void**)&p_y,    g_y);
    cudaGetSymbolAddress((void**)&p_h,    g_h);

    k_embed<<<BL, EE>>>(x, order_h, order_t, pe_w, pe_b, gamma, beta);

    for (int i = 0; i < 2; i++) {
        k_ln<<<BL, EE>>>(ln_g + i*EE, ln_b + i*EE);
        // uz = xn @ inproj^T   (M=16384, N=512, K=128)
        k_sgemm_big<<<dim3((2*DI)/128, BL/128), 256>>>(
            p_xn, inproj_w + (size_t)i*2*DI*EE, p_uz, BL, 2*DI, EE, 0);
        k_conv<<<BL, DI>>>(conv_w + (size_t)i*DI*DC, conv_b + (size_t)i*DI);
        // xdbl = uc @ xproj^T  (M=16384, N=40, K=256)
        k_sgemm_nt<<<dim3(1, BL/64), 256>>>(
            p_uc, xproj_w + (size_t)i*NXD*DI, p_xdbl, BL, NXD, DI);
        k_delta<<<BL, DI>>>(dtproj_w + (size_t)i*DI*DR, dtproj_b + (size_t)i*DI);
        // chunked selective scan
        k_scanA<<<2048, 256>>>(A_log + (size_t)i*DI*DS);
        k_scanB<<<64, 256>>>(A_log + (size_t)i*DI*DS);
        k_scanC<<<2048, 256>>>(A_log + (size_t)i*DI*DS, Dp + (size_t)i*DI);
        // h += y @ outproj^T   (M=16384, N=128, K=256), accumulate
        k_sgemm_big<<<dim3(EE/128, BL/128), 256>>>(
            p_y, outproj_w + (size_t)i*EE*DI, p_h, BL, EE, DI, 1);
    }

    k_zero<<<1, 512>>>();
    k_finacc<<<BB*16, 256>>>(hn_g, hn_b);
    k_fc<<<1, 192>>>(fc_w, fc_b, out);
}

// round 4
// speedup vs baseline: 1.4470x; 1.4470x over previous
#include <cuda_runtime.h>
#include <cuda_bf16.h>
#include <math.h>
#include <stdint.h>

// Problem dims (fixed by setup_inputs)
#define BB   4
#define NPTS 2048
#define LL   4096      // 2*NPTS
#define EE   128
#define DI   256
#define DS   16
#define DR   8
#define NXD  40        // DR + 2*DS
#define DC   4
#define NC   40
#define BL   (BB*LL)   // 16384 rows
#define NCH  32        // scan chunks
#define CL   128       // chunk length
#define NCHAN (BB*DI)  // 1024 scan channels

// -------- scratch (static device globals; no runtime allocation) --------
__device__ float g_h   [(size_t)BL*EE];
__device__ float g_xn  [(size_t)BL*EE];
__device__ float g_uz  [(size_t)BL*2*DI];
__device__ float g_uc  [(size_t)BL*DI];
__device__ float g_xdbl[(size_t)BL*NXD];
__device__ float g_delta[(size_t)BL*DI];
__device__ float g_y   [(size_t)BL*DI];
__device__ float g_acc [BB*EE];
__device__ float g_hend[(size_t)NCHAN*NCH*DS];
__device__ float g_h0  [(size_t)NCHAN*NCH*DS];
__device__ float g_sd  [(size_t)NCHAN*NCH];

__device__ __forceinline__ float siluf(float x) { return x / (1.f + expf(-x)); }
__device__ __forceinline__ float softplusf(float x) {
    return fmaxf(x, 0.f) + log1pf(expf(-fabsf(x)));
}

// -------- 0) gather + positional embed --------
__global__ void k_embed(const float* __restrict__ x,
                        const int* __restrict__ oh, const int* __restrict__ ot,
                        const float* __restrict__ pew, const float* __restrict__ peb,
                        const float* __restrict__ gamma, const float* __restrict__ beta)
{
    int bl = blockIdx.x;
    int b = bl >> 12, l = bl & (LL-1);
    int e = threadIdx.x;
    int gi, idx;
    if (l < NPTS) { gi = 0; idx = oh[b*NPTS + l]; }
    else          { gi = 1; idx = ot[b*NPTS + (l - NPTS)]; }
    const float* p = x + ((size_t)b*NPTS + idx)*3;
    float px = p[0], py = p[1], pz = p[2];
    float v = pew[e*3+0]*px + pew[e*3+1]*py + pew[e*3+2]*pz + peb[e];
    v = v * gamma[gi*EE + e] + beta[gi*EE + e];
    g_h[(size_t)bl*EE + e] = v;
}

// -------- 1) LayerNorm over E=128 --------
__global__ void k_ln(const float* __restrict__ g, const float* __restrict__ bbv)
{
    int row = blockIdx.x;
    int e   = threadIdx.x;
    float v = g_h[(size_t)row*EE + e];
    float a = v, a2 = v*v;
    #pragma unroll
    for (int o = 16; o > 0; o >>= 1) {
        a  += __shfl_xor_sync(~0u, a,  o);
        a2 += __shfl_xor_sync(~0u, a2, o);
    }
    __shared__ float s1[4], s2[4];
    int w = e >> 5;
    if ((e & 31) == 0) { s1[w] = a; s2[w] = a2; }
    __syncthreads();
    float sum  = s1[0] + s1[1] + s1[2] + s1[3];
    float sumq = s2[0] + s2[1] + s2[2] + s2[3];
    float m   = sum  * (1.f/EE);
    float var = sumq * (1.f/EE) - m*m;
    float xn = (v - m) * rsqrtf(var + 1e-5f) * g[e] + bbv[e];
    g_xn[(size_t)row*EE + e] = xn;
}

// ======== tf32 tensor-core GEMM: C[M,N] (+)= A[M,K] * W[N,K]^T ========
// 3-pass precision split (hi*hi + hi*lo + lo*hi), fp32 accumulate.
// BM=128, BN=64, BK=16, 256 threads, 8 warps each computing 32x32.
// Requires M%128==0, K%16==0; N arbitrary (guarded).
__device__ __forceinline__ uint32_t f2tf32(float x) {
    uint32_t r;
    asm("cvt.rna.tf32.f32 %0, %1;" : "=r"(r) : "f"(x));
    return r;
}
__device__ __forceinline__ void mma_tf32(
    float& c0, float& c1, float& c2, float& c3,
    uint32_t a0, uint32_t a1, uint32_t a2, uint32_t a3,
    uint32_t b0, uint32_t b1)
{
    asm volatile(
        "mma.sync.aligned.m16n8k8.row.col.f32.tf32.tf32.f32 "
        "{%0,%1,%2,%3}, {%4,%5,%6,%7}, {%8,%9}, {%0,%1,%2,%3};"
        : "+f"(c0), "+f"(c1), "+f"(c2), "+f"(c3)
        : "r"(a0), "r"(a1), "r"(a2), "r"(a3), "r"(b0), "r"(b1));
}

#define GPAD 17

__global__ __launch_bounds__(256) void k_gemm_tc(
    const float* __restrict__ A, const float* __restrict__ W,
    float* __restrict__ C, int M, int N, int K, int accum)
{
    __shared__ uint32_t sAh[128*GPAD];
    __shared__ uint32_t sAl[128*GPAD];
    __shared__ uint32_t sWh[64*GPAD];
    __shared__ uint32_t sWl[64*GPAD];

    int tid = threadIdx.x;
    int bm = blockIdx.y * 128;
    int bn = blockIdx.x * 64;
    int wid = tid >> 5, lane = tid & 31;
    int wm = (wid & 3) * 32;      // warp row base in tile
    int wn = (wid >> 2) * 32;     // warp col base in tile
    int g  = lane >> 2, tg = lane & 3;

    float acc[2][4][4];
    #pragma unroll
    for (int mt = 0; mt < 2; mt++)
        #pragma unroll
        for (int nt = 0; nt < 4; nt++)
            #pragma unroll
            for (int i = 0; i < 4; i++) acc[mt][nt][i] = 0.f;

    int lr = tid >> 2;            // 0..63
    int lc = (tid & 3) * 4;       // 0,4,8,12

    for (int k0 = 0; k0 < K; k0 += 16) {
        __syncthreads();   // protect smem from previous iteration's readers
        // ---- load + split A tile (128 x 16) ----
        #pragma unroll
        for (int rr = 0; rr < 2; rr++) {
            int row = lr + rr*64;
            float4 v = *(const float4*)(A + (size_t)(bm + row)*K + k0 + lc);
            float xs[4] = {v.x, v.y, v.z, v.w};
            int base = row*GPAD + lc;
            #pragma unroll
            for (int i = 0; i < 4; i++) {
                uint32_t hi = f2tf32(xs[i]);
                float hif = __uint_as_float(hi);
                sAh[base + i] = hi;
                sAl[base + i] = f2tf32(xs[i] - hif);
            }
        }
        // ---- load + split W tile (64 x 16), guard n ----
        {
            int n = bn + lr;
            float4 v = make_float4(0.f, 0.f, 0.f, 0.f);
            if (n < N) v = *(const float4*)(W + (size_t)n*K + k0 + lc);
            float xs[4] = {v.x, v.y, v.z, v.w};
            int base = lr*GPAD + lc;
            #pragma unroll
            for (int i = 0; i < 4; i++) {
                uint32_t hi = f2tf32(xs[i]);
                float hif = __uint_as_float(hi);
                sWh[base + i] = hi;
                sWl[base + i] = f2tf32(xs[i] - hif);
            }
        }
        __syncthreads();

        // ---- two k8 steps ----
        #pragma unroll
        for (int ks = 0; ks < 16; ks += 8) {
            uint32_t ah[2][4], al[2][4];
            #pragma unroll
            for (int mt = 0; mt < 2; mt++) {
                int r = wm + mt*16 + g;
                ah[mt][0] = sAh[(r   )*GPAD + ks + tg    ];
                ah[mt][1] = sAh[(r+8 )*GPAD + ks + tg    ];
                ah[mt][2] = sAh[(r   )*GPAD + ks + tg + 4];
                ah[mt][3] = sAh[(r+8 )*GPAD + ks + tg + 4];
                al[mt][0] = sAl[(r   )*GPAD + ks + tg    ];
                al[mt][1] = sAl[(r+8 )*GPAD + ks + tg    ];
                al[mt][2] = sAl[(r   )*GPAD + ks + tg + 4];
                al[mt][3] = sAl[(r+8 )*GPAD + ks + tg + 4];
            }
            uint32_t bh[4][2], bl[4][2];
            #pragma unroll
            for (int nt = 0; nt < 4; nt++) {
                int n = wn + nt*8 + g;
                bh[nt][0] = sWh[n*GPAD + ks + tg    ];
                bh[nt][1] = sWh[n*GPAD + ks + tg + 4];
                bl[nt][0] = sWl[n*GPAD + ks + tg    ];
                bl[nt][1] = sWl[n*GPAD + ks + tg + 4];
            }
            #pragma unroll
            for (int mt = 0; mt < 2; mt++)
                #pragma unroll
                for (int nt = 0; nt < 4; nt++) {
                    float* c = acc[mt][nt];
                    mma_tf32(c[0], c[1], c[2], c[3],
                             ah[mt][0], ah[mt][1], ah[mt][2], ah[mt][3],
                             bh[nt][0], bh[nt][1]);
                    mma_tf32(c[0], c[1], c[2], c[3],
                             ah[mt][0], ah[mt][1], ah[mt][2], ah[mt][3],
                             bl[nt][0], bl[nt][1]);
                    mma_tf32(c[0], c[1], c[2], c[3],
                             al[mt][0], al[mt][1], al[mt][2], al[mt][3],
                             bh[nt][0], bh[nt][1]);
                }
        }
    }

    // ---- epilogue ----
    #pragma unroll
    for (int mt = 0; mt < 2; mt++) {
        int r0 = bm + wm + mt*16 + g;
        #pragma unroll
        for (int nt = 0; nt < 4; nt++) {
            int col = bn + wn + nt*8 + 2*tg;
            if (col >= N) continue;
            float* p0 = C + (size_t)r0*N + col;
            float* p1 = C + (size_t)(r0+8)*N + col;
            float c0 = acc[mt][nt][0], c1 = acc[mt][nt][1];
            float c2 = acc[mt][nt][2], c3 = acc[mt][nt][3];
            if (accum) { c0 += p0[0]; c1 += p0[1]; c2 += p1[0]; c3 += p1[1]; }
            p0[0] = c0; p0[1] = c1;
            p1[0] = c2; p1[1] = c3;
        }
    }
}

// -------- 2) depthwise causal conv (width 4) + SiLU --------
__global__ void k_conv(const float* __restrict__ cw, const float* __restrict__ cb)
{
    int row = blockIdx.x;
    int d   = threadIdx.x;
    int b = row >> 12, l = row & (LL-1);
    const float* u = g_uz;
    size_t base = ((size_t)b*LL)*(2*DI) + d;
    float w0 = cw[d*DC+0], w1 = cw[d*DC+1], w2 = cw[d*DC+2], w3 = cw[d*DC+3];
    float acc = cb[d];
    if (l >= 3) acc += u[base + (size_t)(l-3)*(2*DI)] * w0;
    if (l >= 2) acc += u[base + (size_t)(l-2)*(2*DI)] * w1;
    if (l >= 1) acc += u[base + (size_t)(l-1)*(2*DI)] * w2;
    acc += u[base + (size_t)l*(2*DI)] * w3;
    g_uc[(size_t)row*DI + d] = siluf(acc);
}

// -------- 3) delta = softplus(dt @ dtw^T + dtb) --------
__global__ void k_delta(const float* __restrict__ dtw, const float* __restrict__ dtb)
{
    int row = blockIdx.x;
    int d   = threadIdx.x;
    __shared__ float dts[DR];
    if (d < DR) dts[d] = g_xdbl[(size_t)row*NXD + d];
    __syncthreads();
    float acc = dtb[d];
    #pragma unroll
    for (int r = 0; r < DR; r++) acc += dts[r] * dtw[d*DR + r];
    g_delta[(size_t)row*DI + d] = softplusf(acc);
}

// -------- 4a) chunk scan pass A --------
__global__ void k_scanA(const float* __restrict__ Alog)
{
    int w    = blockIdx.x * 8 + (threadIdx.x >> 5);
    int lane = threadIdx.x & 31;
    int grp  = lane >> 4;
    int s    = lane & 15;
    int pair = w & 511;
    int c    = w >> 9;
    int chan = pair*2 + grp;
    int b = chan >> 8, d = chan & 255;

    float A = -expf(Alog[d*DS + s]);
    float h = 0.f, sd = 0.f;

    size_t base_du = (size_t)b*LL*DI + d;
    size_t base_x  = (size_t)b*LL*NXD;
    int t0 = c*CL;

    #pragma unroll 4
    for (int tt = 0; tt < CL; tt++) {
        int t = t0 + tt;
        float delta = g_delta[base_du + (size_t)t*DI];
        float u     = g_uc   [base_du + (size_t)t*DI];
        float Bt    = g_xdbl [base_x + (size_t)t*NXD + DR + s];
        float a = expf(delta * A);
        h = a*h + (delta*u)*Bt;
        sd += delta;
    }
    g_hend[((size_t)chan*NCH + c)*DS + s] = h;
    if (s == 0) g_sd[(size_t)chan*NCH + c] = sd;
}

// -------- 4b) stitch chunk initial states --------
__global__ void k_scanB(const float* __restrict__ Alog)
{
    int w    = blockIdx.x * 8 + (threadIdx.x >> 5);
    int lane = threadIdx.x & 31;
    int grp  = lane >> 4;
    int s    = lane & 15;
    int chan = w*2 + grp;
    int d = chan & 255;

    float A = -expf(Alog[d*DS + s]);
    float h0 = 0.f;
    size_t base = (size_t)chan*NCH;
    for (int c = 0; c < NCH; c++) {
        g_h0[(base + c)*DS + s] = h0;
        float P = expf(A * g_sd[base + c]);
        h0 = P*h0 + g_hend[(base + c)*DS + s];
    }
}

// -------- 4c) chunk scan pass C --------
__global__ void k_scanC(const float* __restrict__ Alog, const float* __restrict__ Dpv)
{
    int w    = blockIdx.x * 8 + (threadIdx.x >> 5);
    int lane = threadIdx.x & 31;
    int grp  = lane >> 4;
    int s    = lane & 15;
    int pair = w & 511;
    int c    = w >> 9;
    int chan = pair*2 + grp;
    int b = chan >> 8, d = chan & 255;

    float A  = -expf(Alog[d*DS + s]);
    float Dd = Dpv[d];
    float h  = g_h0[((size_t)chan*NCH + c)*DS + s];

    size_t base_du = (size_t)b*LL*DI + d;
    size_t base_x  = (size_t)b*LL*NXD;
    size_t base_z  = (size_t)b*LL*(2*DI) + DI + d;
    int t0 = c*CL;

    #pragma unroll 2
    for (int tt = 0; tt < CL; tt++) {
        int t = t0 + tt;
        float delta = g_delta[base_du + (size_t)t*DI];
        float u     = g_uc   [base_du + (size_t)t*DI];
        float Bt    = g_xdbl [base_x + (size_t)t*NXD + DR + s];
        float Ct    = g_xdbl [base_x + (size_t)t*NXD + DR + DS + s];
        float a = expf(delta * A);
        h = a*h + (delta*u)*Bt;
        float p = h * Ct;
        p += __shfl_xor_sync(~0u, p, 8, 16);
        p += __shfl_xor_sync(~0u, p, 4, 16);
        p += __shfl_xor_sync(~0u, p, 2, 16);
        p += __shfl_xor_sync(~0u, p, 1, 16);
        if (s == 0) {
            float z = g_uz[base_z + (size_t)t*(2*DI)];
            float y = p + Dd*u;
            y *= siluf(z);
            g_y[base_du + (size_t)t*DI] = y;
        }
    }
}

// -------- 5) final: zero accum, LN+mean accumulate, fc --------
__global__ void k_zero()
{
    int t = threadIdx.x;
    if (t < BB*EE) g_acc[t] = 0.f;
}

__global__ void k_finacc(const float* __restrict__ gg, const float* __restrict__ gb)
{
    int b     = blockIdx.x >> 4;
    int chunk = blockIdx.x & 15;
    int w    = threadIdx.x >> 5;
    int lane = threadIdx.x & 31;
    float g0 = gg[lane], g1 = gg[lane+32], g2 = gg[lane+64], g3 = gg[lane+96];
    float b0 = gb[lane], b1 = gb[lane+32], b2 = gb[lane+64], b3 = gb[lane+96];
    float a0=0.f, a1=0.f, a2=0.f, a3=0.f;
    for (int j = 0; j < 32; j++) {
        int l = chunk*256 + j*8 + w;
        const float* row = g_h + ((size_t)b*LL + l)*EE;
        float x0 = row[lane], x1 = row[lane+32], x2 = row[lane+64], x3 = row[lane+96];
        float sv = x0+x1+x2+x3;
        float sq = x0*x0 + x1*x1 + x2*x2 + x3*x3;
        #pragma unroll
        for (int o = 16; o > 0; o >>= 1) {
            sv += __shfl_xor_sync(~0u, sv, o);
            sq += __shfl_xor_sync(~0u, sq, o);
        }
        float m   = sv * (1.f/EE);
        float var = sq * (1.f/EE) - m*m;
        float inv = rsqrtf(var + 1e-5f);
        a0 += (x0-m)*inv*g0 + b0;
        a1 += (x1-m)*inv*g1 + b1;
        a2 += (x2-m)*inv*g2 + b2;
        a3 += (x3-m)*inv*g3 + b3;
    }
    atomicAdd(&g_acc[b*EE + lane     ], a0);
    atomicAdd(&g_acc[b*EE + lane + 32], a1);
    atomicAdd(&g_acc[b*EE + lane + 64], a2);
    atomicAdd(&g_acc[b*EE + lane + 96], a3);
}

__global__ void k_fc(const float* __restrict__ fcw, const float* __restrict__ fcb,
                     float* __restrict__ out)
{
    int t = threadIdx.x;
    if (t >= BB*NC) return;
    int b = t / NC, c = t % NC;
    float acc = 0.f;
    #pragma unroll 4
    for (int e = 0; e < EE; e++) acc += g_acc[b*EE + e] * fcw[c*EE + e];
    out[t] = acc * (1.f/LL) + fcb[c];
}

// ----------------------------------------------------------------------------
extern "C" void kernel_launch(void* const* d_in, const int* in_sizes, int n_in,
                              void* d_out, int out_size)
{
    const float* x        = (const float*)d_in[0];
    const int*   order_h  = (const int*)  d_in[1];
    const int*   order_t  = (const int*)  d_in[2];
    const float* pe_w     = (const float*)d_in[3];
    const float* pe_b     = (const float*)d_in[4];
    const float* gamma    = (const float*)d_in[5];
    const float* beta     = (const float*)d_in[6];
    const float* ln_g     = (const float*)d_in[7];
    const float* ln_b     = (const float*)d_in[8];
    const float* inproj_w = (const float*)d_in[9];
    const float* conv_w   = (const float*)d_in[10];
    const float* conv_b   = (const float*)d_in[11];
    const float* xproj_w  = (const float*)d_in[12];
    const float* dtproj_w = (const float*)d_in[13];
    const float* dtproj_b = (const float*)d_in[14];
    const float* A_log    = (const float*)d_in[15];
    const float* Dp       = (const float*)d_in[16];
    const float* outproj_w= (const float*)d_in[17];
    const float* hn_g     = (const float*)d_in[18];
    const float* hn_b     = (const float*)d_in[19];
    const float* fc_w     = (const float*)d_in[20];
    const float* fc_b     = (const float*)d_in[21];
    float* out = (float*)d_out;

    float *p_xn, *p_uz, *p_uc, *p_xdbl, *p_y, *p_h;
    cudaGetSymbolAddress((void**)&p_xn,   g_xn);
    cudaGetSymbolAddress((void**)&p_uz,   g_uz);
    cudaGetSymbolAddress((void**)&p_uc,   g_uc);
    cudaGetSymbolAddress((void**)&p_xdbl, g_xdbl);
    cudaGetSymbolAddress((void**)&p_y,    g_y);
    cudaGetSymbolAddress((void**)&p_h,    g_h);

    k_embed<<<BL, EE>>>(x, order_h, order_t, pe_w, pe_b, gamma, beta);

    for (int i = 0; i < 2; i++) {
        k_ln<<<BL, EE>>>(ln_g + i*EE, ln_b + i*EE);
        // uz = xn @ inproj^T   (M=16384, N=512, K=128)
        k_gemm_tc<<<dim3((2*DI)/64, BL/128), 256>>>(
            p_xn, inproj_w + (size_t)i*2*DI*EE, p_uz, BL, 2*DI, EE, 0);
        k_conv<<<BL, DI>>>(conv_w + (size_t)i*DI*DC, conv_b + (size_t)i*DI);
        // xdbl = uc @ xproj^T  (M=16384, N=40, K=256)
        k_gemm_tc<<<dim3(1, BL/128), 256>>>(
            p_uc, xproj_w + (size_t)i*NXD*DI, p_xdbl, BL, NXD, DI, 0);
        k_delta<<<BL, DI>>>(dtproj_w + (size_t)i*DI*DR, dtproj_b + (size_t)i*DI);
        // chunked selective scan
        k_scanA<<<2048, 256>>>(A_log + (size_t)i*DI*DS);
        k_scanB<<<64, 256>>>(A_log + (size_t)i*DI*DS);
        k_scanC<<<2048, 256>>>(A_log + (size_t)i*DI*DS, Dp + (size_t)i*DI);
        // h += y @ outproj^T   (M=16384, N=128, K=256), accumulate
        k_gemm_tc<<<dim3(EE/64, BL/128), 256>>>(
            p_y, outproj_w + (size_t)i*EE*DI, p_h, BL, EE, DI, 1);
    }

    k_zero<<<1, 512>>>();
    k_finacc<<<BB*16, 256>>>(hn_g, hn_b);
    k_fc<<<1, 192>>>(fc_w, fc_b, out);
}